// round 10
// baseline (speedup 1.0000x reference)
#include <cuda_runtime.h>
#include <cuda_fp16.h>
#include <cstdint>

#define BATCH 2048
#define DIN 64
#define HID 512
#define G4 2048
#define KENC 576
#define KDEC 512
#define TIN 336
#define TOUT 96
#define NSTEP (TIN + TOUT)

#define BM 256
#define BN 128
#define GX (G4 / BN)      // 16
#define GY (BATCH / BM)   // 8
#define NCTA (GX * GY)    // 128  (<=148: all co-resident)
#define NTHREADS 256

#define BK 32
#define ASTR 40                         // proj kernel smem stride (halves)
#define WSTR 584                        // W smem row stride (halves), conflict-free
#define W_BYTES (BN * WSTR * 2)         // 149504
#define SMEM_TOTAL W_BYTES

// ---------- device scratch ----------
__device__ __align__(256) __half g_Wenc[G4 * KENC];
__device__ float  g_benc[G4];
__device__ __align__(256) __half g_Wdec0[G4 * KDEC];
__device__ float  g_bdec0[G4];
__device__ __align__(256) __half g_Wdec[G4 * KDEC];
__device__ float  g_bdec[G4];
__device__ __align__(256) __half g_linWt[DIN * HID];
__device__ __align__(256) __half g_x[(size_t)TIN * BATCH * DIN];
__device__ __align__(256) __half g_h0[BATCH * HID];
__device__ __align__(256) __half g_h1[BATCH * HID];
__device__ float  g_c[BATCH * HID];
__device__ __align__(256) __half g_Hdec[(size_t)TOUT * BATCH * HID];
__device__ unsigned g_bar;

// ---------- helpers ----------
__device__ __forceinline__ float rcp_fast(float x) {
    float y; asm("rcp.approx.f32 %0, %1;" : "=f"(y) : "f"(x)); return y;
}
__device__ __forceinline__ float sigmoid_f(float x) { return rcp_fast(1.0f + __expf(-x)); }
__device__ __forceinline__ float tanh_f(float x) { return 1.0f - 2.0f * rcp_fast(1.0f + __expf(2.0f * x)); }

__device__ __forceinline__ void mma_f16(float* c, const uint32_t* a, const uint32_t* b) {
    asm volatile(
        "mma.sync.aligned.m16n8k16.row.col.f32.f16.f16.f32 "
        "{%0,%1,%2,%3}, {%4,%5,%6,%7}, {%8,%9}, {%0,%1,%2,%3};"
        : "+f"(c[0]), "+f"(c[1]), "+f"(c[2]), "+f"(c[3])
        : "r"(a[0]), "r"(a[1]), "r"(a[2]), "r"(a[3]), "r"(b[0]), "r"(b[1]));
}
__device__ __forceinline__ void ldsm_x4(uint32_t* r, uint32_t addr) {
    asm volatile("ldmatrix.sync.aligned.m8n8.x4.shared.b16 {%0,%1,%2,%3}, [%4];"
                 : "=r"(r[0]), "=r"(r[1]), "=r"(r[2]), "=r"(r[3]) : "r"(addr));
}
__device__ __forceinline__ uint32_t ldg32cg(const __half* p) {
    uint32_t v;
    asm volatile("ld.global.cg.b32 %0, [%1];" : "=r"(v) : "l"(p));
    return v;
}
__device__ __forceinline__ void cp16s(uint32_t smem_addr, const __half* gptr) {
    asm volatile("cp.async.cg.shared.global [%0], [%1], 16;" :: "r"(smem_addr), "l"(gptr));
}
#define CP_COMMIT() asm volatile("cp.async.commit_group;" ::: "memory")
#define CP_WAIT0()  asm volatile("cp.async.wait_group 0;" ::: "memory")

// ---------- weight prep: gate interleave (n = 4u+gate) + decoder feedback fusion ----------
__global__ void prep_weights(const float* __restrict__ eWih, const float* __restrict__ eWhh,
                             const float* __restrict__ ebih, const float* __restrict__ ebhh,
                             const float* __restrict__ dWih, const float* __restrict__ dWhh,
                             const float* __restrict__ dbih, const float* __restrict__ dbhh,
                             const float* __restrict__ linW, const float* __restrict__ linb) {
    __shared__ float wih[DIN];
    const int n = blockIdx.x;
    const int u = n >> 2, g = n & 3;
    const int r = g * HID + u;

    for (int d = threadIdx.x; d < DIN; d += blockDim.x) wih[d] = dWih[r * DIN + d];
    __syncthreads();

    for (int k = threadIdx.x; k < KENC; k += blockDim.x) {
        float v = (k < DIN) ? eWih[r * DIN + k] : eWhh[r * HID + (k - DIN)];
        g_Wenc[n * KENC + k] = __float2half(v);
    }
    for (int k = threadIdx.x; k < KDEC; k += blockDim.x) {
        float w0 = dWhh[r * HID + k];
        g_Wdec0[n * KDEC + k] = __float2half(w0);
        float acc = w0;
#pragma unroll 8
        for (int d = 0; d < DIN; d++) acc += wih[d] * linW[d * HID + k];
        g_Wdec[n * KDEC + k] = __float2half(acc);
    }
    if (n < DIN) {
        for (int k = threadIdx.x; k < HID; k += blockDim.x)
            g_linWt[n * HID + k] = __float2half(linW[n * HID + k]);
    }
    if (threadIdx.x == 0) {
        g_benc[n] = ebih[r] + ebhh[r];
        float bd = dbih[r] + dbhh[r];
        g_bdec0[n] = bd;
        float acc = bd;
        for (int d = 0; d < DIN; d++) acc += wih[d] * linb[d];
        g_bdec[n] = acc;
    }
}

__global__ void convert_inputs(const float* __restrict__ inp) {
    size_t i = (size_t)blockIdx.x * blockDim.x + threadIdx.x;
    const size_t N = (size_t)TIN * BATCH * DIN;
    if (i < N) g_x[i] = __float2half(inp[i]);
}

__global__ void init_state() {
    int i = blockIdx.x * blockDim.x + threadIdx.x;
    if (i < BATCH * HID) { g_h0[i] = __float2half(0.0f); g_c[i] = 0.0f; }
    if (i == 0) g_bar = 0u;
}

// ---------- persistent kernel: W in smem, A fragments direct from global, no mainloop barriers ----------
__global__ __launch_bounds__(NTHREADS, 1)
void lstm_persistent() {
    extern __shared__ __align__(16) char smx[];
    const uint32_t wBase = (uint32_t)__cvta_generic_to_shared(smx);  // W: [BN][WSTR] halves

    const int tid = threadIdx.x;
    const int lane = tid & 31, warp = tid >> 5;       // 8 warps
    const int gid = lane >> 2, tig = lane & 3;
    const int warpM = warp >> 1, warpN = warp & 1;    // 4 x 2 (warp tile 64x64)
    const int blockN = blockIdx.x * BN;
    const int blockM = blockIdx.y * BM;

    // ldmatrix per-lane offset for B (halves)
    const int b_off = ((lane & 7) + 8 * ((lane >> 4) & 1)) * WSTR + 8 * ((lane >> 3) & 1);

    auto loadW = [&](const __half* Wsrc, int K) {
        __syncthreads();
        const int cpr = K >> 3;
        const int total = BN * cpr;
        for (int v = tid; v < total; v += NTHREADS) {
            const int r = v / cpr, cc = v - r * cpr;
            cp16s(wBase + (uint32_t)((r * WSTR + cc * 8) * 2),
                  Wsrc + (size_t)(blockN + r) * K + cc * 8);
        }
        CP_COMMIT();
        CP_WAIT0();
        __syncthreads();
    };

    loadW(g_Wenc, KENC);

#pragma unroll 1
    for (int step = 0; step < NSTEP; step++) {
        const bool enc = (step < TIN);
        if (step == TIN)     loadW(g_Wdec0, KDEC);
        if (step == TIN + 1) loadW(g_Wdec, KDEC);

        const int T = enc ? (KENC / BK) : (KDEC / BK);   // 18 / 16 (even)
        const __half* __restrict__ hin  = (step & 1) ? g_h1 : g_h0;
        __half* __restrict__       hout = (step & 1) ? g_h0 : g_h1;
        const float* __restrict__  bias = enc ? g_benc : (step == TIN ? g_bdec0 : g_bdec);
        const __half* __restrict__ x    = enc ? (g_x + (size_t)step * (BATCH * DIN)) : (const __half*)nullptr;
        const int dec_t = enc ? -1 : (step - TIN);

        float acc[4][8][4];
#pragma unroll
        for (int a = 0; a < 4; a++)
#pragma unroll
            for (int b = 0; b < 8; b++)
#pragma unroll
                for (int cc = 0; cc < 4; cc++) acc[a][b][cc] = 0.0f;

        // A-fragment load: tile t -> 32 uint32 regs (exact R4 fragment mapping, global .cg)
        auto loadA = [&](int t, uint32_t* dst) {
            const int kg = t * BK;
            const __half* abase; int ld, koff;
            if (enc && kg < DIN) { abase = x;   ld = DIN; koff = kg; }
            else                 { abase = hin; ld = HID; koff = kg - (enc ? DIN : 0); }
            const int cbase = koff + 2 * tig;
#pragma unroll
            for (int mt = 0; mt < 4; mt++) {
                const __half* rp  = abase + (size_t)(blockM + warpM * 64 + mt * 16 + gid) * ld + cbase;
                const __half* rp8 = rp + 8 * ld;
#pragma unroll
                for (int kk = 0; kk < 2; kk++) {
                    uint32_t* d = dst + (mt * 2 + kk) * 4;
                    d[0] = ldg32cg(rp  + kk * 16);
                    d[1] = ldg32cg(rp8 + kk * 16);
                    d[2] = ldg32cg(rp  + kk * 16 + 8);
                    d[3] = ldg32cg(rp8 + kk * 16 + 8);
                }
            }
        };

        auto computeT = [&](int t, const uint32_t* a) {
            const int colb = t * BK;
#pragma unroll
            for (int kk = 0; kk < 2; kk++) {
                const int k0 = kk * 16;
                uint32_t bF[8][2];
#pragma unroll
                for (int ntp = 0; ntp < 4; ntp++) {
                    const int n0 = warpN * 64 + ntp * 16;
                    uint32_t r[4];
                    ldsm_x4(r, wBase + (uint32_t)((n0 * WSTR + colb + k0 + b_off) * 2));
                    bF[2 * ntp][0] = r[0]; bF[2 * ntp][1] = r[1];
                    bF[2 * ntp + 1][0] = r[2]; bF[2 * ntp + 1][1] = r[3];
                }
#pragma unroll
                for (int nt = 0; nt < 8; nt++)
#pragma unroll
                    for (int mt = 0; mt < 4; mt++)
                        mma_f16(acc[mt][nt], a + (mt * 2 + kk) * 4, bF[nt]);
            }
        };

        uint32_t aP[32], aQ[32];
        loadA(0, aP);
#pragma unroll 1
        for (int t = 0; t < T; t += 2) {
            if (t + 1 < T) loadA(t + 1, aQ);
            computeT(t, aP);
            if (t + 2 < T) loadA(t + 2, aP);
            if (t + 1 < T) computeT(t + 1, aQ);
        }

        // ---- fused LSTM cell epilogue (cols interleaved: 4u+{i,f,g,o}) ----
#pragma unroll
        for (int mt = 0; mt < 4; mt++) {
            const int r0 = blockM + warpM * 64 + mt * 16 + gid;
#pragma unroll
            for (int nt = 0; nt < 8; nt++) {
                const int cb = blockN + warpN * 64 + nt * 8;
                const float b0 = bias[cb + 2 * tig];
                const float b1 = bias[cb + 2 * tig + 1];
                float v0 = acc[mt][nt][0] + b0;
                float v1 = acc[mt][nt][1] + b1;
                float v2 = acc[mt][nt][2] + b0;
                float v3 = acc[mt][nt][3] + b1;
                const float p0 = __shfl_xor_sync(0xffffffffu, v0, 1);
                const float p1 = __shfl_xor_sync(0xffffffffu, v1, 1);
                const float p2 = __shfl_xor_sync(0xffffffffu, v2, 1);
                const float p3 = __shfl_xor_sync(0xffffffffu, v3, 1);
                const bool ev = (tig & 1) == 0;
                const int u = (cb >> 2) + (tig >> 1);
                const int row = ev ? r0 : (r0 + 8);
                const float gi = ev ? v0 : p2;
                const float gf = ev ? v1 : p3;
                const float gg = ev ? p0 : v2;
                const float go = ev ? p1 : v3;
                const size_t idx = (size_t)row * HID + u;
                const float cold = g_c[idx];
                const float si = sigmoid_f(gi);
                const float sf = sigmoid_f(gf);
                const float so = sigmoid_f(go);
                const float cn = fmaf(sf, cold, si * tanh_f(gg));
                const float hn = so * tanh_f(cn);
                g_c[idx] = cn;
                const __half hh = __float2half(hn);
                hout[idx] = hh;
                if (dec_t >= 0) g_Hdec[(size_t)dec_t * (BATCH * HID) + idx] = hh;
            }
        }

        // ---- software grid barrier (step lockstep) ----
        __syncthreads();
        if (tid == 0) {
            __threadfence();
            atomicAdd(&g_bar, 1u);
            const unsigned target = (unsigned)(step + 1) * (unsigned)NCTA;
            while (*(volatile unsigned*)&g_bar < target) {}
            __threadfence();
        }
        __syncthreads();
    }
}

// ---------- final projection: out[96*2048, 64] = Hdec @ linW^T + lin_b (fp16 mma) ----------
__global__ __launch_bounds__(256, 1)
void proj_kernel(const float* __restrict__ linb, float* __restrict__ out) {
    __shared__ __half As[128][ASTR];
    __shared__ __half Bs[64][ASTR];
    const int tid = threadIdx.x;
    const int lane = tid & 31, warp = tid >> 5;
    const int gid = lane >> 2, tig = lane & 3;
    const int blockM = blockIdx.x * 128;
    const int arow = tid >> 2;
    const int acol = (tid & 3) * 8;

    float acc[8][4];
#pragma unroll
    for (int b = 0; b < 8; b++)
#pragma unroll
        for (int cc = 0; cc < 4; cc++) acc[b][cc] = 0.0f;

    uint4 aReg[2]; uint4 bReg;
    auto fetch = [&](int t) {
        const int kg = t * BK;
#pragma unroll
        for (int i = 0; i < 2; i++)
            aReg[i] = *reinterpret_cast<const uint4*>(g_Hdec + (size_t)(blockM + arow + i * 64) * HID + kg + acol);
        bReg = *reinterpret_cast<const uint4*>(g_linWt + (size_t)arow * HID + kg + acol);
    };
    auto store_smem = [&]() {
#pragma unroll
        for (int i = 0; i < 2; i++)
            *reinterpret_cast<uint4*>(&As[arow + i * 64][acol]) = aReg[i];
        if (arow < 64)
            *reinterpret_cast<uint4*>(&Bs[arow][acol]) = bReg;
    };

    const int ktiles = HID / BK;
    fetch(0);
#pragma unroll 1
    for (int t = 0; t < ktiles; t++) {
        __syncthreads();
        store_smem();
        __syncthreads();
        if (t + 1 < ktiles) fetch(t + 1);
#pragma unroll
        for (int kk = 0; kk < 2; kk++) {
            const int k0 = kk * 16;
            uint32_t aF[4];
            const int m = warp * 16 + gid;
            const __half* ap = &As[m][k0 + 2 * tig];
            aF[0] = *reinterpret_cast<const uint32_t*>(ap);
            aF[1] = *reinterpret_cast<const uint32_t*>(ap + 8 * ASTR);
            aF[2] = *reinterpret_cast<const uint32_t*>(ap + 8);
            aF[3] = *reinterpret_cast<const uint32_t*>(ap + 8 * ASTR + 8);
#pragma unroll
            for (int nt = 0; nt < 8; nt++) {
                const __half* bp = &Bs[nt * 8 + gid][k0 + 2 * tig];
                uint32_t bF[2];
                bF[0] = *reinterpret_cast<const uint32_t*>(bp);
                bF[1] = *reinterpret_cast<const uint32_t*>(bp + 8);
                mma_f16(acc[nt], aF, bF);
            }
        }
    }

    const int r0 = blockM + warp * 16 + gid;
#pragma unroll
    for (int nt = 0; nt < 8; nt++) {
        const int c0 = nt * 8 + 2 * tig;
        const float b0 = linb[c0], b1 = linb[c0 + 1];
        out[(size_t)r0 * DIN + c0]           = acc[nt][0] + b0;
        out[(size_t)r0 * DIN + c0 + 1]       = acc[nt][1] + b1;
        out[(size_t)(r0 + 8) * DIN + c0]     = acc[nt][2] + b0;
        out[(size_t)(r0 + 8) * DIN + c0 + 1] = acc[nt][3] + b1;
    }
}

// ---------- launch ----------
extern "C" void kernel_launch(void* const* d_in, const int* in_sizes, int n_in,
                              void* d_out, int out_size) {
    const float* inputs = (const float*)d_in[0];
    const float* eWih = (const float*)d_in[1];
    const float* eWhh = (const float*)d_in[2];
    const float* ebih = (const float*)d_in[3];
    const float* ebhh = (const float*)d_in[4];
    const float* dWih = (const float*)d_in[5];
    const float* dWhh = (const float*)d_in[6];
    const float* dbih = (const float*)d_in[7];
    const float* dbhh = (const float*)d_in[8];
    const float* linW = (const float*)d_in[9];
    const float* linb = (const float*)d_in[10];
    float* out = (float*)d_out;

    cudaFuncSetAttribute(lstm_persistent, cudaFuncAttributeMaxDynamicSharedMemorySize, SMEM_TOTAL);

    prep_weights<<<G4, 256>>>(eWih, eWhh, ebih, ebhh, dWih, dWhh, dbih, dbhh, linW, linb);
    {
        const size_t N = (size_t)TIN * BATCH * DIN;
        convert_inputs<<<(int)((N + 255) / 256), 256>>>(inputs);
    }
    init_state<<<(BATCH * HID + 255) / 256, 256>>>();

    lstm_persistent<<<dim3(GX, GY), NTHREADS, SMEM_TOTAL>>>();

    proj_kernel<<<(TOUT * BATCH) / 128, 256>>>(linb, out);
}

// round 11
// speedup vs baseline: 2.0989x; 2.0989x over previous
#include <cuda_runtime.h>
#include <cuda_fp16.h>
#include <cstdint>

#define BATCH 2048
#define DIN 64
#define HID 512
#define G4 2048
#define KENC 576
#define KDEC 512
#define TIN 336
#define TOUT 96
#define NSTEP (TIN + TOUT)

#define BM 256
#define BN 128
#define GX (G4 / BN)      // 16
#define GY (BATCH / BM)   // 8
#define NCTA (GX * GY)    // 128  (<=148: all co-resident)
#define NTHREADS 256      // 8 warps; warp tile 32 x 128

#define BK 32
#define ASTR 40                         // A-stage row stride (halves)
#define WSTR 584                        // W smem row stride (halves), conflict-free
#define W_BYTES (BN * WSTR * 2)         // 149504
#define WARPA_BYTES (32 * ASTR * 2)     // 2560 per warp per stage
#define ASTAGE_BYTES (8 * WARPA_BYTES)  // 20480
#define NST 3
#define SMEM_TOTAL (W_BYTES + NST * ASTAGE_BYTES)  // 210944 (fit proven R8)

// ---------- device scratch ----------
__device__ __align__(256) __half g_Wenc[G4 * KENC];
__device__ float  g_benc[G4];
__device__ __align__(256) __half g_Wdec0[G4 * KDEC];
__device__ float  g_bdec0[G4];
__device__ __align__(256) __half g_Wdec[G4 * KDEC];
__device__ float  g_bdec[G4];
__device__ __align__(256) __half g_linWt[DIN * HID];
__device__ __align__(256) __half g_x[(size_t)TIN * BATCH * DIN];
__device__ __align__(256) __half g_h0[BATCH * HID];
__device__ __align__(256) __half g_h1[BATCH * HID];
__device__ float  g_c[BATCH * HID];
__device__ __align__(256) __half g_Hdec[(size_t)TOUT * BATCH * HID];
__device__ unsigned g_bar;

// ---------- helpers ----------
__device__ __forceinline__ float rcp_fast(float x) {
    float y; asm("rcp.approx.f32 %0, %1;" : "=f"(y) : "f"(x)); return y;
}
__device__ __forceinline__ float sigmoid_f(float x) { return rcp_fast(1.0f + __expf(-x)); }
__device__ __forceinline__ float tanh_f(float x) { return 1.0f - 2.0f * rcp_fast(1.0f + __expf(2.0f * x)); }

__device__ __forceinline__ void mma_f16(float* c, const uint32_t* a, const uint32_t* b) {
    asm volatile(
        "mma.sync.aligned.m16n8k16.row.col.f32.f16.f16.f32 "
        "{%0,%1,%2,%3}, {%4,%5,%6,%7}, {%8,%9}, {%0,%1,%2,%3};"
        : "+f"(c[0]), "+f"(c[1]), "+f"(c[2]), "+f"(c[3])
        : "r"(a[0]), "r"(a[1]), "r"(a[2]), "r"(a[3]), "r"(b[0]), "r"(b[1]));
}
__device__ __forceinline__ void ldsm_x4(uint32_t* r, uint32_t addr) {
    asm volatile("ldmatrix.sync.aligned.m8n8.x4.shared.b16 {%0,%1,%2,%3}, [%4];"
                 : "=r"(r[0]), "=r"(r[1]), "=r"(r[2]), "=r"(r[3]) : "r"(addr));
}
__device__ __forceinline__ void cp16s(uint32_t smem_addr, const __half* gptr) {
    asm volatile("cp.async.cg.shared.global [%0], [%1], 16;" :: "r"(smem_addr), "l"(gptr));
}
#define CP_COMMIT() asm volatile("cp.async.commit_group;" ::: "memory")
#define CP_WAIT1()  asm volatile("cp.async.wait_group 1;" ::: "memory")
#define CP_WAIT0()  asm volatile("cp.async.wait_group 0;" ::: "memory")

// ---------- weight prep: gate interleave (n = 4u+gate) + decoder feedback fusion ----------
__global__ void prep_weights(const float* __restrict__ eWih, const float* __restrict__ eWhh,
                             const float* __restrict__ ebih, const float* __restrict__ ebhh,
                             const float* __restrict__ dWih, const float* __restrict__ dWhh,
                             const float* __restrict__ dbih, const float* __restrict__ dbhh,
                             const float* __restrict__ linW, const float* __restrict__ linb) {
    __shared__ float wih[DIN];
    const int n = blockIdx.x;
    const int u = n >> 2, g = n & 3;
    const int r = g * HID + u;

    for (int d = threadIdx.x; d < DIN; d += blockDim.x) wih[d] = dWih[r * DIN + d];
    __syncthreads();

    for (int k = threadIdx.x; k < KENC; k += blockDim.x) {
        float v = (k < DIN) ? eWih[r * DIN + k] : eWhh[r * HID + (k - DIN)];
        g_Wenc[n * KENC + k] = __float2half(v);
    }
    for (int k = threadIdx.x; k < KDEC; k += blockDim.x) {
        float w0 = dWhh[r * HID + k];
        g_Wdec0[n * KDEC + k] = __float2half(w0);
        float acc = w0;
#pragma unroll 8
        for (int d = 0; d < DIN; d++) acc += wih[d] * linW[d * HID + k];
        g_Wdec[n * KDEC + k] = __float2half(acc);
    }
    if (n < DIN) {
        for (int k = threadIdx.x; k < HID; k += blockDim.x)
            g_linWt[n * HID + k] = __float2half(linW[n * HID + k]);
    }
    if (threadIdx.x == 0) {
        g_benc[n] = ebih[r] + ebhh[r];
        float bd = dbih[r] + dbhh[r];
        g_bdec0[n] = bd;
        float acc = bd;
        for (int d = 0; d < DIN; d++) acc += wih[d] * linb[d];
        g_bdec[n] = acc;
    }
}

__global__ void convert_inputs(const float* __restrict__ inp) {
    size_t i = (size_t)blockIdx.x * blockDim.x + threadIdx.x;
    const size_t N = (size_t)TIN * BATCH * DIN;
    if (i < N) g_x[i] = __float2half(inp[i]);
}

__global__ void init_state() {
    int i = blockIdx.x * blockDim.x + threadIdx.x;
    if (i < BATCH * HID) { g_h0[i] = __float2half(0.0f); g_c[i] = 0.0f; }
    if (i == 0) g_bar = 0u;
}

// ---------- persistent kernel: W resident, warp-private A staging, barrier-free mainloop ----------
__global__ __launch_bounds__(NTHREADS, 1)
void lstm_persistent() {
    extern __shared__ __align__(16) char smx[];
    const uint32_t wBase = (uint32_t)__cvta_generic_to_shared(smx);
    const uint32_t aBase = wBase + W_BYTES;

    const int tid = threadIdx.x;
    const int lane = tid & 31, warp = tid >> 5;     // 8 warps; warp owns rows warp*32..+32
    const int gid = lane >> 2, tig = lane & 3;
    const int blockN = blockIdx.x * BN;
    const int blockM = blockIdx.y * BM;
    const int wrow0 = blockM + warp * 32;

    // ldmatrix per-lane offsets (halves) — proven R6/R8
    const int a_off = ((lane & 7) + 8 * ((lane >> 3) & 1)) * ASTR + 8 * ((lane >> 4) & 1);
    const int b_off = ((lane & 7) + 8 * ((lane >> 4) & 1)) * WSTR + 8 * ((lane >> 3) & 1);
    const uint32_t aWarp = aBase + (uint32_t)(warp * WARPA_BYTES);

    auto loadW = [&](const __half* Wsrc, int K) {
        __syncthreads();
        CP_WAIT0();
        const int cpr = K >> 3;
        const int total = BN * cpr;
        for (int v = tid; v < total; v += NTHREADS) {
            const int r = v / cpr, cc = v - r * cpr;
            cp16s(wBase + (uint32_t)((r * WSTR + cc * 8) * 2),
                  Wsrc + (size_t)(blockN + r) * K + cc * 8);
        }
        CP_COMMIT();
        CP_WAIT0();
        __syncthreads();
    };

    loadW(g_Wenc, KENC);

#pragma unroll 1
    for (int step = 0; step < NSTEP; step++) {
        const bool enc = (step < TIN);
        if (step == TIN)     loadW(g_Wdec0, KDEC);
        if (step == TIN + 1) loadW(g_Wdec, KDEC);

        const int T = enc ? (KENC / BK) : (KDEC / BK);   // 18 / 16
        const __half* __restrict__ hin  = (step & 1) ? g_h1 : g_h0;
        __half* __restrict__       hout = (step & 1) ? g_h0 : g_h1;
        const float* __restrict__  bias = enc ? g_benc : (step == TIN ? g_bdec0 : g_bdec);
        const __half* __restrict__ x    = enc ? (g_x + (size_t)step * (BATCH * DIN)) : (const __half*)nullptr;
        const int dec_t = enc ? -1 : (step - TIN);

        float acc[2][16][4];
#pragma unroll
        for (int a = 0; a < 2; a++)
#pragma unroll
            for (int b = 0; b < 16; b++)
#pragma unroll
                for (int cc = 0; cc < 4; cc++) acc[a][b][cc] = 0.0f;

        // warp-private A stage fill: 32 rows x 32 halves, chunk-major for sector efficiency
        auto issueA = [&](int t) {
            const uint32_t stage = aWarp + (uint32_t)((t % NST) * ASTAGE_BYTES);
            const int kg = t * BK;
            const __half* abase; int ld, koff;
            if (enc && kg < DIN) { abase = x;   ld = DIN; koff = kg; }
            else                 { abase = hin; ld = HID; koff = kg - (enc ? DIN : 0); }
#pragma unroll
            for (int i = 0; i < 4; i++) {
                const int v = i * 32 + lane;
                const int r = v >> 2, c8 = (v & 3) * 8;
                cp16s(stage + (uint32_t)((r * ASTR + c8) * 2),
                      abase + (size_t)(wrow0 + r) * ld + koff + c8);
            }
            CP_COMMIT();
        };

        auto computeT = [&](int t) {
            const uint32_t As = aWarp + (uint32_t)((t % NST) * ASTAGE_BYTES);
            const int colb = t * BK;
#pragma unroll
            for (int kk = 0; kk < 2; kk++) {
                const int k0 = kk * 16;
                uint32_t aF[2][4];
#pragma unroll
                for (int mt = 0; mt < 2; mt++)
                    ldsm_x4(aF[mt], As + (uint32_t)((mt * 16 * ASTR + k0 + a_off) * 2));
                uint32_t bF[16][2];
#pragma unroll
                for (int ntp = 0; ntp < 8; ntp++) {
                    const int n0 = ntp * 16;
                    uint32_t r[4];
                    ldsm_x4(r, wBase + (uint32_t)((n0 * WSTR + colb + k0 + b_off) * 2));
                    bF[2 * ntp][0] = r[0]; bF[2 * ntp][1] = r[1];
                    bF[2 * ntp + 1][0] = r[2]; bF[2 * ntp + 1][1] = r[3];
                }
#pragma unroll
                for (int nt = 0; nt < 16; nt++)
#pragma unroll
                    for (int mt = 0; mt < 2; mt++) mma_f16(acc[mt][nt], aF[mt], bF[nt]);
            }
        };

        issueA(0);
        issueA(1);
#pragma unroll 1
        for (int t = 0; t < T; t++) {
            CP_WAIT1();          // own group t done
            __syncwarp();        // other lanes' group t done + smem visibility
            if (t + 2 < T) issueA(t + 2);   // stage (t+2)%3 == (t-1)%3, consumed by this warp
            else CP_COMMIT();               // keep one group per iteration for wait accounting
            computeT(t);
        }

        // ---- fused LSTM cell epilogue (cols interleaved: 4u+{i,f,g,o}) ----
#pragma unroll
        for (int mt = 0; mt < 2; mt++) {
            const int r0 = wrow0 + mt * 16 + gid;
#pragma unroll
            for (int nt = 0; nt < 16; nt++) {
                const int cb = blockN + nt * 8;
                const float b0 = bias[cb + 2 * tig];
                const float b1 = bias[cb + 2 * tig + 1];
                float v0 = acc[mt][nt][0] + b0;
                float v1 = acc[mt][nt][1] + b1;
                float v2 = acc[mt][nt][2] + b0;
                float v3 = acc[mt][nt][3] + b1;
                const float p0 = __shfl_xor_sync(0xffffffffu, v0, 1);
                const float p1 = __shfl_xor_sync(0xffffffffu, v1, 1);
                const float p2 = __shfl_xor_sync(0xffffffffu, v2, 1);
                const float p3 = __shfl_xor_sync(0xffffffffu, v3, 1);
                const bool ev = (tig & 1) == 0;
                const int u = (cb >> 2) + (tig >> 1);
                const int row = ev ? r0 : (r0 + 8);
                const float gi = ev ? v0 : p2;
                const float gf = ev ? v1 : p3;
                const float gg = ev ? p0 : v2;
                const float go = ev ? p1 : v3;
                const size_t idx = (size_t)row * HID + u;
                const float cold = g_c[idx];
                const float si = sigmoid_f(gi);
                const float sf = sigmoid_f(gf);
                const float so = sigmoid_f(go);
                const float cn = fmaf(sf, cold, si * tanh_f(gg));
                const float hn = so * tanh_f(cn);
                g_c[idx] = cn;
                const __half hh = __float2half(hn);
                hout[idx] = hh;
                if (dec_t >= 0) g_Hdec[(size_t)dec_t * (BATCH * HID) + idx] = hh;
            }
        }

        // ---- software grid barrier (step lockstep) ----
        __syncthreads();
        if (tid == 0) {
            __threadfence();
            atomicAdd(&g_bar, 1u);
            const unsigned target = (unsigned)(step + 1) * (unsigned)NCTA;
            while (*(volatile unsigned*)&g_bar < target) {}
            __threadfence();
        }
        __syncthreads();
    }
}

// ---------- final projection: out[96*2048, 64] = Hdec @ linW^T + lin_b (fp16 mma) ----------
__global__ __launch_bounds__(256, 1)
void proj_kernel(const float* __restrict__ linb, float* __restrict__ out) {
    __shared__ __half As[128][ASTR];
    __shared__ __half Bs[64][ASTR];
    const int tid = threadIdx.x;
    const int lane = tid & 31, warp = tid >> 5;
    const int gid = lane >> 2, tig = lane & 3;
    const int blockM = blockIdx.x * 128;
    const int arow = tid >> 2;
    const int acol = (tid & 3) * 8;

    float acc[8][4];
#pragma unroll
    for (int b = 0; b < 8; b++)
#pragma unroll
        for (int cc = 0; cc < 4; cc++) acc[b][cc] = 0.0f;

    uint4 aReg[2]; uint4 bReg;
    auto fetch = [&](int t) {
        const int kg = t * BK;
#pragma unroll
        for (int i = 0; i < 2; i++)
            aReg[i] = *reinterpret_cast<const uint4*>(g_Hdec + (size_t)(blockM + arow + i * 64) * HID + kg + acol);
        bReg = *reinterpret_cast<const uint4*>(g_linWt + (size_t)arow * HID + kg + acol);
    };
    auto store_smem = [&]() {
#pragma unroll
        for (int i = 0; i < 2; i++)
            *reinterpret_cast<uint4*>(&As[arow + i * 64][acol]) = aReg[i];
        if (arow < 64)
            *reinterpret_cast<uint4*>(&Bs[arow][acol]) = bReg;
    };

    const int ktiles = HID / BK;
    fetch(0);
#pragma unroll 1
    for (int t = 0; t < ktiles; t++) {
        __syncthreads();
        store_smem();
        __syncthreads();
        if (t + 1 < ktiles) fetch(t + 1);
#pragma unroll
        for (int kk = 0; kk < 2; kk++) {
            const int k0 = kk * 16;
            uint32_t aF[4];
            const int m = warp * 16 + gid;
            const __half* ap = &As[m][k0 + 2 * tig];
            aF[0] = *reinterpret_cast<const uint32_t*>(ap);
            aF[1] = *reinterpret_cast<const uint32_t*>(ap + 8 * ASTR);
            aF[2] = *reinterpret_cast<const uint32_t*>(ap + 8);
            aF[3] = *reinterpret_cast<const uint32_t*>(ap + 8 * ASTR + 8);
#pragma unroll
            for (int nt = 0; nt < 8; nt++) {
                const __half* bp = &Bs[nt * 8 + gid][k0 + 2 * tig];
                uint32_t bF[2];
                bF[0] = *reinterpret_cast<const uint32_t*>(bp);
                bF[1] = *reinterpret_cast<const uint32_t*>(bp + 8);
                mma_f16(acc[nt], aF, bF);
            }
        }
    }

    const int r0 = blockM + warp * 16 + gid;
#pragma unroll
    for (int nt = 0; nt < 8; nt++) {
        const int c0 = nt * 8 + 2 * tig;
        const float b0 = linb[c0], b1 = linb[c0 + 1];
        out[(size_t)r0 * DIN + c0]           = acc[nt][0] + b0;
        out[(size_t)r0 * DIN + c0 + 1]       = acc[nt][1] + b1;
        out[(size_t)(r0 + 8) * DIN + c0]     = acc[nt][2] + b0;
        out[(size_t)(r0 + 8) * DIN + c0 + 1] = acc[nt][3] + b1;
    }
}

// ---------- launch ----------
extern "C" void kernel_launch(void* const* d_in, const int* in_sizes, int n_in,
                              void* d_out, int out_size) {
    const float* inputs = (const float*)d_in[0];
    const float* eWih = (const float*)d_in[1];
    const float* eWhh = (const float*)d_in[2];
    const float* ebih = (const float*)d_in[3];
    const float* ebhh = (const float*)d_in[4];
    const float* dWih = (const float*)d_in[5];
    const float* dWhh = (const float*)d_in[6];
    const float* dbih = (const float*)d_in[7];
    const float* dbhh = (const float*)d_in[8];
    const float* linW = (const float*)d_in[9];
    const float* linb = (const float*)d_in[10];
    float* out = (float*)d_out;

    cudaFuncSetAttribute(lstm_persistent, cudaFuncAttributeMaxDynamicSharedMemorySize, SMEM_TOTAL);

    prep_weights<<<G4, 256>>>(eWih, eWhh, ebih, ebhh, dWih, dWhh, dbih, dbhh, linW, linb);
    {
        const size_t N = (size_t)TIN * BATCH * DIN;
        convert_inputs<<<(int)((N + 255) / 256), 256>>>(inputs);
    }
    init_state<<<(BATCH * HID + 255) / 256, 256>>>();

    lstm_persistent<<<dim3(GX, GY), NTHREADS, SMEM_TOTAL>>>();

    proj_kernel<<<(TOUT * BATCH) / 128, 256>>>(linb, out);
}

// round 12
// speedup vs baseline: 2.1037x; 1.0023x over previous
#include <cuda_runtime.h>
#include <cuda_fp16.h>
#include <cstdint>

#define BATCH 2048
#define DIN 64
#define HID 512
#define G4 2048
#define KENC 576
#define KDEC 512
#define TIN 336
#define TOUT 96
#define NSTEP (TIN + TOUT)

#define BM 256
#define BN 128
#define GX (G4 / BN)      // 16
#define GY (BATCH / BM)   // 8
#define NCTA (GX * GY)    // 128  (<=148: all co-resident)
#define NTHREADS 256      // 8 warps; warp tile 32 x 128

#define BK 32
#define ASTR 40                         // A-stage row stride (halves)
#define WSTR 584                        // W smem row stride (halves), conflict-free
#define W_BYTES (BN * WSTR * 2)         // 149504
#define WARPA_BYTES (32 * ASTR * 2)     // 2560 per warp per stage
#define ASTAGE_BYTES (8 * WARPA_BYTES)  // 20480
#define NST 3
#define SMEM_TOTAL (W_BYTES + NST * ASTAGE_BYTES)  // 210944 (fit proven R8)

// ---------- device scratch ----------
__device__ __align__(256) __half g_Wenc[G4 * KENC];
__device__ float  g_benc[G4];
__device__ __align__(256) __half g_Wdec0[G4 * KDEC];
__device__ float  g_bdec0[G4];
__device__ __align__(256) __half g_Wdec[G4 * KDEC];
__device__ float  g_bdec[G4];
__device__ __align__(256) __half g_linWt[DIN * HID];
__device__ __align__(256) __half g_x[(size_t)TIN * BATCH * DIN];
__device__ __align__(256) __half g_h0[BATCH * HID];
__device__ __align__(256) __half g_h1[BATCH * HID];
__device__ float  g_c[BATCH * HID];
__device__ __align__(256) __half g_Hdec[(size_t)TOUT * BATCH * HID];
__device__ unsigned g_bar;

// ---------- helpers ----------
__device__ __forceinline__ float rcp_fast(float x) {
    float y; asm("rcp.approx.f32 %0, %1;" : "=f"(y) : "f"(x)); return y;
}
__device__ __forceinline__ float sigmoid_f(float x) { return rcp_fast(1.0f + __expf(-x)); }
__device__ __forceinline__ float tanh_f(float x) { return 1.0f - 2.0f * rcp_fast(1.0f + __expf(2.0f * x)); }

__device__ __forceinline__ void mma_f16(float* c, const uint32_t* a, const uint32_t* b) {
    asm volatile(
        "mma.sync.aligned.m16n8k16.row.col.f32.f16.f16.f32 "
        "{%0,%1,%2,%3}, {%4,%5,%6,%7}, {%8,%9}, {%0,%1,%2,%3};"
        : "+f"(c[0]), "+f"(c[1]), "+f"(c[2]), "+f"(c[3])
        : "r"(a[0]), "r"(a[1]), "r"(a[2]), "r"(a[3]), "r"(b[0]), "r"(b[1]));
}
__device__ __forceinline__ void ldsm_x4(uint32_t* r, uint32_t addr) {
    asm volatile("ldmatrix.sync.aligned.m8n8.x4.shared.b16 {%0,%1,%2,%3}, [%4];"
                 : "=r"(r[0]), "=r"(r[1]), "=r"(r[2]), "=r"(r[3]) : "r"(addr));
}
__device__ __forceinline__ void cp16s(uint32_t smem_addr, const __half* gptr) {
    asm volatile("cp.async.cg.shared.global [%0], [%1], 16;" :: "r"(smem_addr), "l"(gptr));
}
#define CP_COMMIT() asm volatile("cp.async.commit_group;" ::: "memory")
#define CP_WAIT1()  asm volatile("cp.async.wait_group 1;" ::: "memory")
#define CP_WAIT0()  asm volatile("cp.async.wait_group 0;" ::: "memory")

// ---------- weight prep: gate interleave (n = 4u+gate) + decoder feedback fusion ----------
__global__ void prep_weights(const float* __restrict__ eWih, const float* __restrict__ eWhh,
                             const float* __restrict__ ebih, const float* __restrict__ ebhh,
                             const float* __restrict__ dWih, const float* __restrict__ dWhh,
                             const float* __restrict__ dbih, const float* __restrict__ dbhh,
                             const float* __restrict__ linW, const float* __restrict__ linb) {
    __shared__ float wih[DIN];
    const int n = blockIdx.x;
    const int u = n >> 2, g = n & 3;
    const int r = g * HID + u;

    for (int d = threadIdx.x; d < DIN; d += blockDim.x) wih[d] = dWih[r * DIN + d];
    __syncthreads();

    for (int k = threadIdx.x; k < KENC; k += blockDim.x) {
        float v = (k < DIN) ? eWih[r * DIN + k] : eWhh[r * HID + (k - DIN)];
        g_Wenc[n * KENC + k] = __float2half(v);
    }
    for (int k = threadIdx.x; k < KDEC; k += blockDim.x) {
        float w0 = dWhh[r * HID + k];
        g_Wdec0[n * KDEC + k] = __float2half(w0);
        float acc = w0;
#pragma unroll 8
        for (int d = 0; d < DIN; d++) acc += wih[d] * linW[d * HID + k];
        g_Wdec[n * KDEC + k] = __float2half(acc);
    }
    if (n < DIN) {
        for (int k = threadIdx.x; k < HID; k += blockDim.x)
            g_linWt[n * HID + k] = __float2half(linW[n * HID + k]);
    }
    if (threadIdx.x == 0) {
        g_benc[n] = ebih[r] + ebhh[r];
        float bd = dbih[r] + dbhh[r];
        g_bdec0[n] = bd;
        float acc = bd;
        for (int d = 0; d < DIN; d++) acc += wih[d] * linb[d];
        g_bdec[n] = acc;
    }
}

__global__ void convert_inputs(const float* __restrict__ inp) {
    size_t i = (size_t)blockIdx.x * blockDim.x + threadIdx.x;
    const size_t N = (size_t)TIN * BATCH * DIN;
    if (i < N) g_x[i] = __float2half(inp[i]);
}

__global__ void init_state() {
    int i = blockIdx.x * blockDim.x + threadIdx.x;
    if (i < BATCH * HID) { g_h0[i] = __float2half(0.0f); g_c[i] = 0.0f; }
    if (i == 0) g_bar = 0u;
}

// ---------- persistent kernel: W resident, warp-private A staging, barrier-free mainloop ----------
__global__ __launch_bounds__(NTHREADS, 1)
void lstm_persistent() {
    extern __shared__ __align__(16) char smx[];
    const uint32_t wBase = (uint32_t)__cvta_generic_to_shared(smx);
    const uint32_t aBase = wBase + W_BYTES;

    const int tid = threadIdx.x;
    const int lane = tid & 31, warp = tid >> 5;     // 8 warps; warp owns rows warp*32..+32
    const int gid = lane >> 2, tig = lane & 3;
    const int blockN = blockIdx.x * BN;
    const int blockM = blockIdx.y * BM;
    const int wrow0 = blockM + warp * 32;

    // ldmatrix per-lane offsets (halves) — proven R6/R8
    const int a_off = ((lane & 7) + 8 * ((lane >> 3) & 1)) * ASTR + 8 * ((lane >> 4) & 1);
    const int b_off = ((lane & 7) + 8 * ((lane >> 4) & 1)) * WSTR + 8 * ((lane >> 3) & 1);
    const uint32_t aWarp = aBase + (uint32_t)(warp * WARPA_BYTES);

    auto loadW = [&](const __half* Wsrc, int K) {
        __syncthreads();
        CP_WAIT0();
        const int cpr = K >> 3;
        const int total = BN * cpr;
        for (int v = tid; v < total; v += NTHREADS) {
            const int r = v / cpr, cc = v - r * cpr;
            cp16s(wBase + (uint32_t)((r * WSTR + cc * 8) * 2),
                  Wsrc + (size_t)(blockN + r) * K + cc * 8);
        }
        CP_COMMIT();
        CP_WAIT0();
        __syncthreads();
    };

    loadW(g_Wenc, KENC);

#pragma unroll 1
    for (int step = 0; step < NSTEP; step++) {
        const bool enc = (step < TIN);
        if (step == TIN)     loadW(g_Wdec0, KDEC);
        if (step == TIN + 1) loadW(g_Wdec, KDEC);

        const int T = enc ? (KENC / BK) : (KDEC / BK);   // 18 / 16
        const __half* __restrict__ hin  = (step & 1) ? g_h1 : g_h0;
        __half* __restrict__       hout = (step & 1) ? g_h0 : g_h1;
        const float* __restrict__  bias = enc ? g_benc : (step == TIN ? g_bdec0 : g_bdec);
        const __half* __restrict__ x    = enc ? (g_x + (size_t)step * (BATCH * DIN)) : (const __half*)nullptr;
        const int dec_t = enc ? -1 : (step - TIN);

        float acc[2][16][4];
#pragma unroll
        for (int a = 0; a < 2; a++)
#pragma unroll
            for (int b = 0; b < 16; b++)
#pragma unroll
                for (int cc = 0; cc < 4; cc++) acc[a][b][cc] = 0.0f;

        // warp-private A stage fill: 32 rows x 32 halves, chunk-major for sector efficiency
        auto issueA = [&](int t) {
            const uint32_t stage = aWarp + (uint32_t)((t % NST) * ASTAGE_BYTES);
            const int kg = t * BK;
            const __half* abase; int ld, koff;
            if (enc && kg < DIN) { abase = x;   ld = DIN; koff = kg; }
            else                 { abase = hin; ld = HID; koff = kg - (enc ? DIN : 0); }
#pragma unroll
            for (int i = 0; i < 4; i++) {
                const int v = i * 32 + lane;
                const int r = v >> 2, c8 = (v & 3) * 8;
                cp16s(stage + (uint32_t)((r * ASTR + c8) * 2),
                      abase + (size_t)(wrow0 + r) * ld + koff + c8);
            }
            CP_COMMIT();
        };

        auto computeT = [&](int t) {
            const uint32_t As = aWarp + (uint32_t)((t % NST) * ASTAGE_BYTES);
            const int colb = t * BK;
#pragma unroll
            for (int kk = 0; kk < 2; kk++) {
                const int k0 = kk * 16;
                uint32_t aF[2][4];
#pragma unroll
                for (int mt = 0; mt < 2; mt++)
                    ldsm_x4(aF[mt], As + (uint32_t)((mt * 16 * ASTR + k0 + a_off) * 2));
                uint32_t bF[16][2];
#pragma unroll
                for (int ntp = 0; ntp < 8; ntp++) {
                    const int n0 = ntp * 16;
                    uint32_t r[4];
                    ldsm_x4(r, wBase + (uint32_t)((n0 * WSTR + colb + k0 + b_off) * 2));
                    bF[2 * ntp][0] = r[0]; bF[2 * ntp][1] = r[1];
                    bF[2 * ntp + 1][0] = r[2]; bF[2 * ntp + 1][1] = r[3];
                }
#pragma unroll
                for (int nt = 0; nt < 16; nt++)
#pragma unroll
                    for (int mt = 0; mt < 2; mt++) mma_f16(acc[mt][nt], aF[mt], bF[nt]);
            }
        };

        issueA(0);
        issueA(1);
#pragma unroll 1
        for (int t = 0; t < T; t++) {
            CP_WAIT1();          // own group t done
            __syncwarp();        // other lanes' group t done + smem visibility
            if (t + 2 < T) issueA(t + 2);   // stage (t+2)%3 == (t-1)%3, consumed by this warp
            else CP_COMMIT();               // keep one group per iteration for wait accounting
            computeT(t);
        }

        // ---- fused LSTM cell epilogue (cols interleaved: 4u+{i,f,g,o}) ----
#pragma unroll
        for (int mt = 0; mt < 2; mt++) {
            const int r0 = wrow0 + mt * 16 + gid;
#pragma unroll
            for (int nt = 0; nt < 16; nt++) {
                const int cb = blockN + nt * 8;
                const float b0 = bias[cb + 2 * tig];
                const float b1 = bias[cb + 2 * tig + 1];
                float v0 = acc[mt][nt][0] + b0;
                float v1 = acc[mt][nt][1] + b1;
                float v2 = acc[mt][nt][2] + b0;
                float v3 = acc[mt][nt][3] + b1;
                const float p0 = __shfl_xor_sync(0xffffffffu, v0, 1);
                const float p1 = __shfl_xor_sync(0xffffffffu, v1, 1);
                const float p2 = __shfl_xor_sync(0xffffffffu, v2, 1);
                const float p3 = __shfl_xor_sync(0xffffffffu, v3, 1);
                const bool ev = (tig & 1) == 0;
                const int u = (cb >> 2) + (tig >> 1);
                const int row = ev ? r0 : (r0 + 8);
                const float gi = ev ? v0 : p2;
                const float gf = ev ? v1 : p3;
                const float gg = ev ? p0 : v2;
                const float go = ev ? p1 : v3;
                const size_t idx = (size_t)row * HID + u;
                const float cold = g_c[idx];
                const float si = sigmoid_f(gi);
                const float sf = sigmoid_f(gf);
                const float so = sigmoid_f(go);
                const float cn = fmaf(sf, cold, si * tanh_f(gg));
                const float hn = so * tanh_f(cn);
                g_c[idx] = cn;
                const __half hh = __float2half(hn);
                hout[idx] = hh;
                if (dec_t >= 0) g_Hdec[(size_t)dec_t * (BATCH * HID) + idx] = hh;
            }
        }

        // ---- software grid barrier (step lockstep) ----
        __syncthreads();
        if (tid == 0) {
            __threadfence();
            atomicAdd(&g_bar, 1u);
            const unsigned target = (unsigned)(step + 1) * (unsigned)NCTA;
            while (*(volatile unsigned*)&g_bar < target) {}
            __threadfence();
        }
        __syncthreads();
    }
}

// ---------- final projection: out[96*2048, 64] = Hdec @ linW^T + lin_b (fp16 mma) ----------
__global__ __launch_bounds__(256, 1)
void proj_kernel(const float* __restrict__ linb, float* __restrict__ out) {
    __shared__ __half As[128][ASTR];
    __shared__ __half Bs[64][ASTR];
    const int tid = threadIdx.x;
    const int lane = tid & 31, warp = tid >> 5;
    const int gid = lane >> 2, tig = lane & 3;
    const int blockM = blockIdx.x * 128;
    const int arow = tid >> 2;
    const int acol = (tid & 3) * 8;

    float acc[8][4];
#pragma unroll
    for (int b = 0; b < 8; b++)
#pragma unroll
        for (int cc = 0; cc < 4; cc++) acc[b][cc] = 0.0f;

    uint4 aReg[2]; uint4 bReg;
    auto fetch = [&](int t) {
        const int kg = t * BK;
#pragma unroll
        for (int i = 0; i < 2; i++)
            aReg[i] = *reinterpret_cast<const uint4*>(g_Hdec + (size_t)(blockM + arow + i * 64) * HID + kg + acol);
        bReg = *reinterpret_cast<const uint4*>(g_linWt + (size_t)arow * HID + kg + acol);
    };
    auto store_smem = [&]() {
#pragma unroll
        for (int i = 0; i < 2; i++)
            *reinterpret_cast<uint4*>(&As[arow + i * 64][acol]) = aReg[i];
        if (arow < 64)
            *reinterpret_cast<uint4*>(&Bs[arow][acol]) = bReg;
    };

    const int ktiles = HID / BK;
    fetch(0);
#pragma unroll 1
    for (int t = 0; t < ktiles; t++) {
        __syncthreads();
        store_smem();
        __syncthreads();
        if (t + 1 < ktiles) fetch(t + 1);
#pragma unroll
        for (int kk = 0; kk < 2; kk++) {
            const int k0 = kk * 16;
            uint32_t aF[4];
            const int m = warp * 16 + gid;
            const __half* ap = &As[m][k0 + 2 * tig];
            aF[0] = *reinterpret_cast<const uint32_t*>(ap);
            aF[1] = *reinterpret_cast<const uint32_t*>(ap + 8 * ASTR);
            aF[2] = *reinterpret_cast<const uint32_t*>(ap + 8);
            aF[3] = *reinterpret_cast<const uint32_t*>(ap + 8 * ASTR + 8);
#pragma unroll
            for (int nt = 0; nt < 8; nt++) {
                const __half* bp = &Bs[nt * 8 + gid][k0 + 2 * tig];
                uint32_t bF[2];
                bF[0] = *reinterpret_cast<const uint32_t*>(bp);
                bF[1] = *reinterpret_cast<const uint32_t*>(bp + 8);
                mma_f16(acc[nt], aF, bF);
            }
        }
    }

    const int r0 = blockM + warp * 16 + gid;
#pragma unroll
    for (int nt = 0; nt < 8; nt++) {
        const int c0 = nt * 8 + 2 * tig;
        const float b0 = linb[c0], b1 = linb[c0 + 1];
        out[(size_t)r0 * DIN + c0]           = acc[nt][0] + b0;
        out[(size_t)r0 * DIN + c0 + 1]       = acc[nt][1] + b1;
        out[(size_t)(r0 + 8) * DIN + c0]     = acc[nt][2] + b0;
        out[(size_t)(r0 + 8) * DIN + c0 + 1] = acc[nt][3] + b1;
    }
}

// ---------- launch ----------
extern "C" void kernel_launch(void* const* d_in, const int* in_sizes, int n_in,
                              void* d_out, int out_size) {
    const float* inputs = (const float*)d_in[0];
    const float* eWih = (const float*)d_in[1];
    const float* eWhh = (const float*)d_in[2];
    const float* ebih = (const float*)d_in[3];
    const float* ebhh = (const float*)d_in[4];
    const float* dWih = (const float*)d_in[5];
    const float* dWhh = (const float*)d_in[6];
    const float* dbih = (const float*)d_in[7];
    const float* dbhh = (const float*)d_in[8];
    const float* linW = (const float*)d_in[9];
    const float* linb = (const float*)d_in[10];
    float* out = (float*)d_out;

    cudaFuncSetAttribute(lstm_persistent, cudaFuncAttributeMaxDynamicSharedMemorySize, SMEM_TOTAL);

    prep_weights<<<G4, 256>>>(eWih, eWhh, ebih, ebhh, dWih, dWhh, dbih, dbhh, linW, linb);
    {
        const size_t N = (size_t)TIN * BATCH * DIN;
        convert_inputs<<<(int)((N + 255) / 256), 256>>>(inputs);
    }
    init_state<<<(BATCH * HID + 255) / 256, 256>>>();

    lstm_persistent<<<dim3(GX, GY), NTHREADS, SMEM_TOTAL>>>();

    proj_kernel<<<(TOUT * BATCH) / 128, 256>>>(linb, out);
}